// round 11
// baseline (speedup 1.0000x reference)
#include <cuda_runtime.h>
#include <math.h>

// Problem constants
#define N_    8
#define A_    16368
#define K_    200
#define B_    20
#define PIX   16384           // 128*128
#define G_    8               // k-values per main item (4 packed k-pairs in regs)
#define GRP   (K_ / G_)       // 25
#define CHQ   8               // pixel chunks per (n,kg) group
#define CHPIX (PIX / CHQ)     // 2048 px per main item
#define NI_MAIN (N_ * GRP * CHQ)   // 1600
#define NI_Y    (N_ * 8)           // 64
#define NI_MISC (N_)               // 8
#define NITEMS  (NI_MAIN + NI_Y + NI_MISC)  // 1672
#define T1    256
#define NBLK  592             // persistent blocks (148 SMs x ~4)
#define ITERS_I (CHPIX / (T1 * 2))  // 4 iterations, 2 px/thread per main item

__device__ float g_partials[NBLK];
__device__ unsigned int g_next;    // work queue cursor (zero-init; reset by last block)
__device__ unsigned int g_count;   // completion counter (zero-init; reset by last block)

typedef unsigned long long u64;
#define SGN2 0x8000000080000000ULL

__device__ __forceinline__ float ex2f_(float x) {
    float r; asm("ex2.approx.ftz.f32 %0, %1;" : "=f"(r) : "f"(x)); return r;
}
__device__ __forceinline__ float lg2f_(float x) {
    float r; asm("lg2.approx.ftz.f32 %0, %1;" : "=f"(r) : "f"(x)); return r;
}
// packed f32x2 ops (Blackwell FFMA2 path — PTX-only)
__device__ __forceinline__ u64 fma2_(u64 a, u64 b, u64 c) {
    u64 r; asm("fma.rn.f32x2 %0, %1, %2, %3;" : "=l"(r) : "l"(a), "l"(b), "l"(c)); return r;
}
__device__ __forceinline__ u64 mul2_(u64 a, u64 b) {
    u64 r; asm("mul.rn.f32x2 %0, %1, %2;" : "=l"(r) : "l"(a), "l"(b)); return r;
}
__device__ __forceinline__ u64 add2_(u64 a, u64 b) {
    u64 r; asm("add.rn.f32x2 %0, %1, %2;" : "=l"(r) : "l"(a), "l"(b)); return r;
}
__device__ __forceinline__ void unpack2_(u64 v, float& a, float& b) {
    unsigned lo, hi;
    asm("mov.b64 {%0, %1}, %2;" : "=r"(lo), "=r"(hi) : "l"(v));
    a = __uint_as_float(lo); b = __uint_as_float(hi);
}
__device__ __forceinline__ u64 pack2s_(float x, float y) {
    u64 r; unsigned ux = __float_as_uint(x), uy = __float_as_uint(y);
    asm("mov.b64 %0, {%1, %2};" : "=l"(r) : "r"(ux), "r"(uy));
    return r;
}
__device__ __forceinline__ u64 bcast2_(float v) {
    return pack2s_(v, v);
}

#define LOG2E   1.4426950408889634f
#define LN2     0.6931471805599453f
#define LOG10_2 0.3010299956639812f
#define WM  (LN2 / ((float)PIX * (float)N_ * (float)K_))
#define WP  (1.0f / ((float)N_ * K_ * K_))
#define WN  (1.0f / ((float)N_ * 3.0f * K_ * K_))
#define WL  (1.0f / ((float)N_ * K_))

// One pixel, 8 k-values (4 packed pairs). Updates accM0/accM1 (packed -|z|) and acc_lg.
__device__ __forceinline__ void pixel_work(
    float f0, float f1, float f2, float f3,
    const u64* C0, const u64* C1, const u64* C2, const u64* C3,
    u64& accM0, u64& accM1, float& acc_lg)
{
    u64 P0 = bcast2_(f0);
    u64 P1 = bcast2_(f1);
    u64 P2 = bcast2_(f2);
    u64 P3 = bcast2_(f3);
    float t0, t1, t2, t3;
    {
        u64 z = fma2_(C0[0], P0, fma2_(C1[0], P1, fma2_(C2[0], P2, mul2_(C3[0], P3))));
        u64 m = z | SGN2;
        accM0 = add2_(accM0, m);
        float m0, m1; unpack2_(m, m0, m1);
        t0 = (1.0f + ex2f_(m0)) * (1.0f + ex2f_(m1));
    }
    {
        u64 z = fma2_(C0[1], P0, fma2_(C1[1], P1, fma2_(C2[1], P2, mul2_(C3[1], P3))));
        u64 m = z | SGN2;
        accM1 = add2_(accM1, m);
        float m0, m1; unpack2_(m, m0, m1);
        t1 = (1.0f + ex2f_(m0)) * (1.0f + ex2f_(m1));
    }
    {
        u64 z = fma2_(C0[2], P0, fma2_(C1[2], P1, fma2_(C2[2], P2, mul2_(C3[2], P3))));
        u64 m = z | SGN2;
        accM0 = add2_(accM0, m);
        float m0, m1; unpack2_(m, m0, m1);
        t2 = (1.0f + ex2f_(m0)) * (1.0f + ex2f_(m1));
    }
    {
        u64 z = fma2_(C0[3], P0, fma2_(C1[3], P1, fma2_(C2[3], P2, mul2_(C3[3], P3))));
        u64 m = z | SGN2;
        accM1 = add2_(accM1, m);
        float m0, m1; unpack2_(m, m0, m1);
        t3 = (1.0f + ex2f_(m0)) * (1.0f + ex2f_(m1));
    }
    // one LG2 per 8 elements: each factor in (1,2], product <= 256
    acc_lg += lg2f_((t0 * t1) * (t2 * t3));
}

__global__ __launch_bounds__(T1, 3)
void allloss_kernel(const float* __restrict__ map_class,
                    const float* __restrict__ map_box,
                    const float* __restrict__ map_coef,
                    const float* __restrict__ proto,
                    const float* __restrict__ anchor_center,
                    const float* __restrict__ anchor_hw,
                    const float* __restrict__ gt_boxes,
                    const float* __restrict__ gt_masks,
                    const int*   __restrict__ pos_idx,
                    const int*   __restrict__ neg_idx,
                    const int*   __restrict__ gt_idx,
                    float*       __restrict__ out)
{
    const int tid = threadIdx.x;

    __shared__ float  red[T1];
    __shared__ int    s_item;
    __shared__ float  ck[K_][4];      // y items
    __shared__ int    bk[K_];
    __shared__ float  Cb[B_][4];
    __shared__ float  Ct[4];

    float partial = 0.0f;

    // ===== persistent work-queue loop =====
    for (;;) {
        if (tid == 0) s_item = (int)atomicAdd(&g_next, 1u);
        __syncthreads();
        const int item = s_item;
        __syncthreads();
        if (item >= NITEMS) break;

        if (item < NI_MAIN) {
            // ===== main mask term: sum of lg2(1+2^-|z|) + 0.5*|z| =====
            const int n   = item / (GRP * CHQ);
            const int rem = item % (GRP * CHQ);
            const int kg  = rem / CHQ;
            const int ch  = rem % CHQ;

            u64 C0[4], C1[4], C2[4], C3[4];
#pragma unroll
            for (int kp = 0; kp < 4; ++kp) {
                int a0 = pos_idx[n * K_ + kg * G_ + kp * 2 + 0];
                int a1 = pos_idx[n * K_ + kg * G_ + kp * 2 + 1];
                float4 ca = *(const float4*)(map_coef + ((size_t)n * A_ + a0) * 4);
                float4 cb = *(const float4*)(map_coef + ((size_t)n * A_ + a1) * 4);
                C0[kp] = pack2s_(ca.x * LOG2E, cb.x * LOG2E);
                C1[kp] = pack2s_(ca.y * LOG2E, cb.y * LOG2E);
                C2[kp] = pack2s_(ca.z * LOG2E, cb.z * LOG2E);
                C3[kp] = pack2s_(ca.w * LOG2E, cb.w * LOG2E);
            }

            const float* pb = proto + (size_t)n * 4 * PIX;
            const int base = ch * CHPIX + tid * 2;

            u64   accM0 = 0ull, accM1 = 0ull;
            float acc_lg = 0.0f;

#pragma unroll 1
            for (int it = 0; it < ITERS_I; ++it) {   // 4 iterations, 2 px/thread
                int pix = base + it * (T1 * 2);
                float2 r0 = *(const float2*)(pb + 0 * PIX + pix);
                float2 r1 = *(const float2*)(pb + 1 * PIX + pix);
                float2 r2 = *(const float2*)(pb + 2 * PIX + pix);
                float2 r3 = *(const float2*)(pb + 3 * PIX + pix);
                pixel_work(r0.x, r1.x, r2.x, r3.x, C0, C1, C2, C3, accM0, accM1, acc_lg);
                pixel_work(r0.y, r1.y, r2.y, r3.y, C0, C1, C2, C3, accM0, accM1, acc_lg);
            }
            u64 accM = add2_(accM0, accM1);
            float mx, my;
            unpack2_(accM, mx, my);
            partial += (acc_lg - 0.5f * (mx + my)) * WM;

        } else if (item < NI_MAIN + NI_Y) {
            // ===== y-term and 0.5*Sum z:  sum_pix [ 0.5*(Ctot.p) - sum_b y_b*(C_b.p) ] =====
            const int b2  = item - NI_MAIN;
            const int n   = b2 >> 3;
            const int ch8 = b2 & 7;

            if (tid < K_) {
                int a = pos_idx[n * K_ + tid];
                const float* cp = map_coef + ((size_t)n * A_ + a) * 4;
                ck[tid][0] = cp[0] * LOG2E; ck[tid][1] = cp[1] * LOG2E;
                ck[tid][2] = cp[2] * LOG2E; ck[tid][3] = cp[3] * LOG2E;
                bk[tid] = gt_idx[n * K_ + tid];
            }
            __syncthreads();
            if (tid < B_ * 4) {
                int b = tid >> 2, j = tid & 3;
                float s = 0.0f;
                for (int k = 0; k < K_; ++k)
                    if (bk[k] == b) s += ck[k][j];
                Cb[b][j] = s;
            }
            __syncthreads();
            if (tid < 4) {
                float s = 0.0f;
                for (int b = 0; b < B_; ++b) s += Cb[b][tid];
                Ct[tid] = s;
            }
            __syncthreads();

            const float* pb = proto + (size_t)n * 4 * PIX;
            const float* gm = gt_masks + (size_t)n * B_ * PIX;
            float accD = 0.0f, accE = 0.0f;
#pragma unroll 1
            for (int it = 0; it < 2; ++it) {
                int pix = ch8 * 2048 + (it * T1 + tid) * 4;
                float4 p0 = *(const float4*)(pb + 0 * PIX + pix);
                float4 p1 = *(const float4*)(pb + 1 * PIX + pix);
                float4 p2 = *(const float4*)(pb + 2 * PIX + pix);
                float4 p3 = *(const float4*)(pb + 3 * PIX + pix);
                float t0 = Ct[0], t1 = Ct[1], t2 = Ct[2], t3 = Ct[3];
                accE += fmaf(t0, p0.x, fmaf(t1, p1.x, fmaf(t2, p2.x, t3 * p3.x)));
                accE += fmaf(t0, p0.y, fmaf(t1, p1.y, fmaf(t2, p2.y, t3 * p3.y)));
                accE += fmaf(t0, p0.z, fmaf(t1, p1.z, fmaf(t2, p2.z, t3 * p3.z)));
                accE += fmaf(t0, p0.w, fmaf(t1, p1.w, fmaf(t2, p2.w, t3 * p3.w)));
#pragma unroll
                for (int b = 0; b < B_; ++b) {
                    float4 y = *(const float4*)(gm + (size_t)b * PIX + pix);
                    float cb0 = Cb[b][0], cb1 = Cb[b][1], cb2 = Cb[b][2], cb3 = Cb[b][3];
                    float Zx = fmaf(cb0, p0.x, fmaf(cb1, p1.x, fmaf(cb2, p2.x, cb3 * p3.x)));
                    float Zy = fmaf(cb0, p0.y, fmaf(cb1, p1.y, fmaf(cb2, p2.y, cb3 * p3.y)));
                    float Zz = fmaf(cb0, p0.z, fmaf(cb1, p1.z, fmaf(cb2, p2.z, cb3 * p3.z)));
                    float Zw = fmaf(cb0, p0.w, fmaf(cb1, p1.w, fmaf(cb2, p2.w, cb3 * p3.w)));
                    accD = fmaf(y.x, Zx, accD);
                    accD = fmaf(y.y, Zy, accD);
                    accD = fmaf(y.z, Zz, accD);
                    accD = fmaf(y.w, Zw, accD);
                }
            }
            partial += (0.5f * accE - accD) * WM;
            __syncthreads();   // protect shared ck/bk/Cb/Ct before possible reuse

        } else {
            // ===== cls (pos+neg) + loc for one image =====
            const int n = item - NI_MAIN - NI_Y;
            const float EPS = 1e-7f;
            float s = 0.0f;

            if (tid < K_) {
                int a = pos_idx[n * K_ + tid];
                float p = map_class[n * A_ + a];
                p = fminf(fmaxf(p, EPS), 1.0f - EPS);
                s += -lg2f_(p) * (LN2 * WP);

                int gi = gt_idx[n * K_ + tid];
                const float* pr = map_box + ((size_t)n * A_ + a) * 4;
                const float* gt = gt_boxes + ((size_t)n * B_ + gi) * 4;
                float ac0 = anchor_center[a * 2 + 0];
                float ac1 = anchor_center[a * 2 + 1];
                float ah  = anchor_hw[a * 2 + 0];
                float aw  = anchor_hw[a * 2 + 1];
                float t0 = (gt[0] - ac0) / ah;
                float t1 = (gt[1] - ac1) / aw;
                float t2 = lg2f_(gt[2] / ah) * LOG10_2;
                float t3 = lg2f_(gt[3] / aw) * LOG10_2;
                float d, ad, l = 0.0f;
                d = pr[0] - t0; ad = fabsf(d); l += (ad < 1.0f) ? 0.5f * d * d : ad - 0.5f;
                d = pr[1] - t1; ad = fabsf(d); l += (ad < 1.0f) ? 0.5f * d * d : ad - 0.5f;
                d = pr[2] - t2; ad = fabsf(d); l += (ad < 1.0f) ? 0.5f * d * d : ad - 0.5f;
                d = pr[3] - t3; ad = fabsf(d); l += (ad < 1.0f) ? 0.5f * d * d : ad - 0.5f;
                s += l * WL;
            }
            for (int i = tid; i < 3 * K_; i += T1) {
                int a = neg_idx[n * 3 * K_ + i];
                float p = map_class[n * A_ + a];
                p = fminf(fmaxf(p, EPS), 1.0f - EPS);
                s += -lg2f_(1.0f - p) * (LN2 * WN);
            }
            partial += s;
        }
    }

    // ===== one block reduction at the end =====
    red[tid] = partial;
    __syncthreads();
#pragma unroll
    for (int st = T1 / 2; st > 0; st >>= 1) {
        if (tid < st) red[tid] += red[tid + st];
        __syncthreads();
    }
    if (tid == 0) g_partials[blockIdx.x] = red[0];

    // ===== last-block final reduction =====
    __shared__ bool isLast;
    if (tid == 0) {
        __threadfence();
        unsigned int old = atomicAdd(&g_count, 1u);
        isLast = (old == NBLK - 1);
    }
    __syncthreads();
    if (isLast) {
        float s = 0.0f;
        for (int i = tid; i < NBLK; i += T1) s += g_partials[i];
        red[tid] = s;
        __syncthreads();
#pragma unroll
        for (int st = T1 / 2; st > 0; st >>= 1) {
            if (tid < st) red[tid] += red[tid + st];
            __syncthreads();
        }
        if (tid == 0) {
            out[0] = red[0];
            g_next  = 0;   // reset queue for next graph replay
            g_count = 0;
        }
    }
}

extern "C" void kernel_launch(void* const* d_in, const int* in_sizes, int n_in,
                              void* d_out, int out_size)
{
    const float* map_class     = (const float*)d_in[0];
    const float* map_box       = (const float*)d_in[1];
    const float* map_coef      = (const float*)d_in[2];
    const float* proto         = (const float*)d_in[3];
    const float* anchor_center = (const float*)d_in[4];
    const float* anchor_hw     = (const float*)d_in[5];
    const float* gt_boxes      = (const float*)d_in[6];
    const float* gt_masks      = (const float*)d_in[7];
    const int*   pos_idx       = (const int*)d_in[8];
    const int*   neg_idx       = (const int*)d_in[9];
    const int*   gt_idx        = (const int*)d_in[10];
    float* out = (float*)d_out;

    allloss_kernel<<<NBLK, T1>>>(map_class, map_box, map_coef, proto,
                                 anchor_center, anchor_hw, gt_boxes, gt_masks,
                                 pos_idx, neg_idx, gt_idx, out);
}

// round 12
// speedup vs baseline: 1.0910x; 1.0910x over previous
#include <cuda_runtime.h>
#include <math.h>

// Problem constants
#define N_    8
#define A_    16368
#define K_    200
#define B_    20
#define PIX   16384           // 128*128
#define G_    8               // k-values per main block ({c,c} coeffs in regs)
#define GRP   (K_ / G_)       // 25
#define CH_   4               // pixel chunks per (n, k-group)
#define CHPIX (PIX / CH_)     // 4096
#define NB_MAIN (N_ * GRP * CH_)   // 800
#define NB_Y    (N_ * 8)           // 64
#define NB_MISC (N_)               // 8
#define NPART   (NB_MAIN + NB_Y + NB_MISC)  // 872
#define T1    256

__device__ float g_partials[NPART];
__device__ unsigned int g_count;   // zero-init; reset by final block each call

typedef unsigned long long u64;
#define SGN2 0x8000000080000000ULL

__device__ __forceinline__ float ex2f_(float x) {
    float r; asm("ex2.approx.ftz.f32 %0, %1;" : "=f"(r) : "f"(x)); return r;
}
__device__ __forceinline__ float lg2f_(float x) {
    float r; asm("lg2.approx.ftz.f32 %0, %1;" : "=f"(r) : "f"(x)); return r;
}
// packed f32x2 ops (Blackwell FFMA2 path — PTX-only)
__device__ __forceinline__ u64 fma2_(u64 a, u64 b, u64 c) {
    u64 r; asm("fma.rn.f32x2 %0, %1, %2, %3;" : "=l"(r) : "l"(a), "l"(b), "l"(c)); return r;
}
__device__ __forceinline__ u64 mul2_(u64 a, u64 b) {
    u64 r; asm("mul.rn.f32x2 %0, %1, %2;" : "=l"(r) : "l"(a), "l"(b)); return r;
}
__device__ __forceinline__ u64 add2_(u64 a, u64 b) {
    u64 r; asm("add.rn.f32x2 %0, %1, %2;" : "=l"(r) : "l"(a), "l"(b)); return r;
}
__device__ __forceinline__ void unpack2_(u64 v, float& a, float& b) {
    unsigned lo, hi;
    asm("mov.b64 {%0, %1}, %2;" : "=r"(lo), "=r"(hi) : "l"(v));
    a = __uint_as_float(lo); b = __uint_as_float(hi);
}
__device__ __forceinline__ u64 pack2s_(float x, float y) {
    u64 r; unsigned ux = __float_as_uint(x), uy = __float_as_uint(y);
    asm("mov.b64 %0, {%1, %2};" : "=l"(r) : "r"(ux), "r"(uy));
    return r;
}
__device__ __forceinline__ u64 bcast2_(float v) {
    return pack2s_(v, v);
}

#define LOG2E   1.4426950408889634f
#define LN2     0.6931471805599453f
#define LOG10_2 0.3010299956639812f
#define WM  (LN2 / ((float)PIX * (float)N_ * (float)K_))
#define WP  (1.0f / ((float)N_ * K_ * K_))
#define WN  (1.0f / ((float)N_ * 3.0f * K_ * K_))
#define WL  (1.0f / ((float)N_ * K_))

__global__ __launch_bounds__(T1, 2)
void allloss_kernel(const float* __restrict__ map_class,
                    const float* __restrict__ map_box,
                    const float* __restrict__ map_coef,
                    const float* __restrict__ proto,
                    const float* __restrict__ anchor_center,
                    const float* __restrict__ anchor_hw,
                    const float* __restrict__ gt_boxes,
                    const float* __restrict__ gt_masks,
                    const int*   __restrict__ pos_idx,
                    const int*   __restrict__ neg_idx,
                    const int*   __restrict__ gt_idx,
                    float*       __restrict__ out)
{
    const int bid = blockIdx.x;
    const int tid = threadIdx.x;

    __shared__ float  red[T1];
    __shared__ float  ck[K_][4];      // y blocks
    __shared__ int    bk[K_];
    __shared__ float  Cb[B_][4];
    __shared__ float  Ct[4];

    float partial = 0.0f;

    if (bid < NB_MAIN) {
        // ===== main mask term: sum of lg2(1+2^-|z|) + 0.5*|z|  (0.5*z in y-blocks) =====
        const int n   = bid / (GRP * CH_);
        const int rem = bid % (GRP * CH_);
        const int kg  = rem / CH_;
        const int ch  = rem % CH_;

        // 8 coefficient sets, broadcast-packed {c,c}, in registers (64 regs)
        u64 D0[G_], D1[G_], D2[G_], D3[G_];
#pragma unroll
        for (int k = 0; k < G_; ++k) {
            int a = pos_idx[n * K_ + kg * G_ + k];
            float4 cp = *(const float4*)(map_coef + ((size_t)n * A_ + a) * 4);
            D0[k] = bcast2_(cp.x * LOG2E);
            D1[k] = bcast2_(cp.y * LOG2E);
            D2[k] = bcast2_(cp.z * LOG2E);
            D3[k] = bcast2_(cp.w * LOG2E);
        }

        const float* pb = proto + (size_t)n * 4 * PIX;
        u64   accM0 = 0ull, accM1 = 0ull;   // packed sums of -|z|
        float acc_lg = 0.0f;

#pragma unroll 1
        for (int it = 0; it < CHPIX / (T1 * 4); ++it) {    // 4 iterations, 4 pixels/thread
            int pix = ch * CHPIX + (it * T1 + tid) * 4;
            ulonglong2 q0 = *(const ulonglong2*)(pb + 0 * PIX + pix);
            ulonglong2 q1 = *(const ulonglong2*)(pb + 1 * PIX + pix);
            ulonglong2 q2 = *(const ulonglong2*)(pb + 2 * PIX + pix);
            ulonglong2 q3 = *(const ulonglong2*)(pb + 3 * PIX + pix);

            float pA[G_], pB[G_];
#pragma unroll
            for (int k = 0; k < G_; ++k) {
                u64 zA = fma2_(D0[k], q0.x, fma2_(D1[k], q1.x, fma2_(D2[k], q2.x, mul2_(D3[k], q3.x))));
                u64 zB = fma2_(D0[k], q0.y, fma2_(D1[k], q1.y, fma2_(D2[k], q2.y, mul2_(D3[k], q3.y))));
                u64 mA = zA | SGN2;          // packed -|z| (pixels 0,1)
                u64 mB = zB | SGN2;          // packed -|z| (pixels 2,3)
                accM0 = add2_(accM0, mA);
                accM1 = add2_(accM1, mB);
                float a0, a1, b0, b1;
                unpack2_(mA, a0, a1);
                unpack2_(mB, b0, b1);
                float eA0 = ex2f_(a0), eA1 = ex2f_(a1);
                float eB0 = ex2f_(b0), eB1 = ex2f_(b1);
                // (1+e0)(1+e1) = 1 + (e0+e1) + e0*e1
                pA[k] = fmaf(eA0, eA1, eA0 + eA1) + 1.0f;
                pB[k] = fmaf(eB0, eB1, eB0 + eB1) + 1.0f;
            }
            float tA = ((pA[0] * pA[1]) * (pA[2] * pA[3])) * ((pA[4] * pA[5]) * (pA[6] * pA[7]));
            float tB = ((pB[0] * pB[1]) * (pB[2] * pB[3])) * ((pB[4] * pB[5]) * (pB[6] * pB[7]));
            // one LG2 per 32 elements: 32 factors in (1,2], product <= 2^32
            acc_lg += lg2f_(tA * tB);
        }
        u64 accM = add2_(accM0, accM1);
        float mx, my;
        unpack2_(accM, mx, my);
        // Sum|z| = -(mx+my)
        partial = (acc_lg - 0.5f * (mx + my)) * WM;

    } else if (bid < NB_MAIN + NB_Y) {
        // ===== y-term and 0.5*Sum z term:  sum_pix [ 0.5*(Ctot.p) - sum_b y_b*(C_b.p) ] =====
        const int b2  = bid - NB_MAIN;
        const int n   = b2 >> 3;
        const int ch8 = b2 & 7;

        if (tid < K_) {
            int a = pos_idx[n * K_ + tid];
            const float* cp = map_coef + ((size_t)n * A_ + a) * 4;
            ck[tid][0] = cp[0] * LOG2E; ck[tid][1] = cp[1] * LOG2E;
            ck[tid][2] = cp[2] * LOG2E; ck[tid][3] = cp[3] * LOG2E;
            bk[tid] = gt_idx[n * K_ + tid];
        }
        __syncthreads();
        if (tid < B_ * 4) {
            int b = tid >> 2, j = tid & 3;
            float s = 0.0f;
            for (int k = 0; k < K_; ++k)
                if (bk[k] == b) s += ck[k][j];
            Cb[b][j] = s;
        }
        __syncthreads();
        if (tid < 4) {
            float s = 0.0f;
            for (int b = 0; b < B_; ++b) s += Cb[b][tid];
            Ct[tid] = s;
        }
        __syncthreads();

        const float* pb = proto + (size_t)n * 4 * PIX;
        const float* gm = gt_masks + (size_t)n * B_ * PIX;
        float accD = 0.0f, accE = 0.0f;
#pragma unroll 1
        for (int it = 0; it < 2; ++it) {
            int pix = ch8 * 2048 + (it * T1 + tid) * 4;
            float4 p0 = *(const float4*)(pb + 0 * PIX + pix);
            float4 p1 = *(const float4*)(pb + 1 * PIX + pix);
            float4 p2 = *(const float4*)(pb + 2 * PIX + pix);
            float4 p3 = *(const float4*)(pb + 3 * PIX + pix);
            float t0 = Ct[0], t1 = Ct[1], t2 = Ct[2], t3 = Ct[3];
            accE += fmaf(t0, p0.x, fmaf(t1, p1.x, fmaf(t2, p2.x, t3 * p3.x)));
            accE += fmaf(t0, p0.y, fmaf(t1, p1.y, fmaf(t2, p2.y, t3 * p3.y)));
            accE += fmaf(t0, p0.z, fmaf(t1, p1.z, fmaf(t2, p2.z, t3 * p3.z)));
            accE += fmaf(t0, p0.w, fmaf(t1, p1.w, fmaf(t2, p2.w, t3 * p3.w)));
#pragma unroll
            for (int b = 0; b < B_; ++b) {
                float4 y = *(const float4*)(gm + (size_t)b * PIX + pix);
                float cb0 = Cb[b][0], cb1 = Cb[b][1], cb2 = Cb[b][2], cb3 = Cb[b][3];
                float Zx = fmaf(cb0, p0.x, fmaf(cb1, p1.x, fmaf(cb2, p2.x, cb3 * p3.x)));
                float Zy = fmaf(cb0, p0.y, fmaf(cb1, p1.y, fmaf(cb2, p2.y, cb3 * p3.y)));
                float Zz = fmaf(cb0, p0.z, fmaf(cb1, p1.z, fmaf(cb2, p2.z, cb3 * p3.z)));
                float Zw = fmaf(cb0, p0.w, fmaf(cb1, p1.w, fmaf(cb2, p2.w, cb3 * p3.w)));
                accD = fmaf(y.x, Zx, accD);
                accD = fmaf(y.y, Zy, accD);
                accD = fmaf(y.z, Zz, accD);
                accD = fmaf(y.w, Zw, accD);
            }
        }
        partial = (0.5f * accE - accD) * WM;

    } else {
        // ===== cls (pos+neg) + loc for one image =====
        const int n = bid - NB_MAIN - NB_Y;
        const float EPS = 1e-7f;
        float s = 0.0f;

        if (tid < K_) {
            int a = pos_idx[n * K_ + tid];
            float p = map_class[n * A_ + a];
            p = fminf(fmaxf(p, EPS), 1.0f - EPS);
            s += -lg2f_(p) * (LN2 * WP);

            int gi = gt_idx[n * K_ + tid];
            const float* pr = map_box + ((size_t)n * A_ + a) * 4;
            const float* gt = gt_boxes + ((size_t)n * B_ + gi) * 4;
            float ac0 = anchor_center[a * 2 + 0];
            float ac1 = anchor_center[a * 2 + 1];
            float ah  = anchor_hw[a * 2 + 0];
            float aw  = anchor_hw[a * 2 + 1];
            float t0 = (gt[0] - ac0) / ah;
            float t1 = (gt[1] - ac1) / aw;
            float t2 = lg2f_(gt[2] / ah) * LOG10_2;
            float t3 = lg2f_(gt[3] / aw) * LOG10_2;
            float d, ad, l = 0.0f;
            d = pr[0] - t0; ad = fabsf(d); l += (ad < 1.0f) ? 0.5f * d * d : ad - 0.5f;
            d = pr[1] - t1; ad = fabsf(d); l += (ad < 1.0f) ? 0.5f * d * d : ad - 0.5f;
            d = pr[2] - t2; ad = fabsf(d); l += (ad < 1.0f) ? 0.5f * d * d : ad - 0.5f;
            d = pr[3] - t3; ad = fabsf(d); l += (ad < 1.0f) ? 0.5f * d * d : ad - 0.5f;
            s += l * WL;
        }
        for (int i = tid; i < 3 * K_; i += T1) {
            int a = neg_idx[n * 3 * K_ + i];
            float p = map_class[n * A_ + a];
            p = fminf(fmaxf(p, EPS), 1.0f - EPS);
            s += -lg2f_(1.0f - p) * (LN2 * WN);
        }
        partial = s;
    }

    // ===== block reduction =====
    red[tid] = partial;
    __syncthreads();
#pragma unroll
    for (int st = T1 / 2; st > 0; st >>= 1) {
        if (tid < st) red[tid] += red[tid + st];
        __syncthreads();
    }
    if (tid == 0) g_partials[bid] = red[0];

    // ===== last-block final reduction =====
    __shared__ bool isLast;
    if (tid == 0) {
        __threadfence();
        unsigned int old = atomicAdd(&g_count, 1u);
        isLast = (old == NPART - 1);
    }
    __syncthreads();
    if (isLast) {
        float s = 0.0f;
        for (int i = tid; i < NPART; i += T1) s += g_partials[i];
        red[tid] = s;
        __syncthreads();
#pragma unroll
        for (int st = T1 / 2; st > 0; st >>= 1) {
            if (tid < st) red[tid] += red[tid + st];
            __syncthreads();
        }
        if (tid == 0) {
            out[0] = red[0];
            g_count = 0;
        }
    }
}

extern "C" void kernel_launch(void* const* d_in, const int* in_sizes, int n_in,
                              void* d_out, int out_size)
{
    const float* map_class     = (const float*)d_in[0];
    const float* map_box       = (const float*)d_in[1];
    const float* map_coef      = (const float*)d_in[2];
    const float* proto         = (const float*)d_in[3];
    const float* anchor_center = (const float*)d_in[4];
    const float* anchor_hw     = (const float*)d_in[5];
    const float* gt_boxes      = (const float*)d_in[6];
    const float* gt_masks      = (const float*)d_in[7];
    const int*   pos_idx       = (const int*)d_in[8];
    const int*   neg_idx       = (const int*)d_in[9];
    const int*   gt_idx        = (const int*)d_in[10];
    float* out = (float*)d_out;

    allloss_kernel<<<NPART, T1>>>(map_class, map_box, map_coef, proto,
                                  anchor_center, anchor_hw, gt_boxes, gt_masks,
                                  pos_idx, neg_idx, gt_idx, out);
}

// round 13
// speedup vs baseline: 1.1854x; 1.0865x over previous
#include <cuda_runtime.h>
#include <cuda_fp16.h>
#include <math.h>

// Problem constants
#define N_    8
#define A_    16368
#define K_    200
#define B_    20
#define PIX   16384           // 128*128
#define G_    8               // k-values per main block (4 packed k-pairs in regs)
#define GRP   (K_ / G_)       // 25
#define CH_   4               // pixel chunks per (n, k-group)
#define CHPIX (PIX / CH_)     // 4096
#define NB_MAIN (N_ * GRP * CH_)   // 800
#define NB_Y    (N_ * 8)           // 64
#define NB_MISC (N_)               // 8
#define NPART   (NB_MAIN + NB_Y + NB_MISC)  // 872
#define T1    256
#define ITERS (CHPIX / (T1 * 2))   // 8 iterations, 2 pixels/thread

__device__ float g_partials[NPART];
__device__ unsigned int g_count;   // zero-init; reset by final block each call

typedef unsigned long long u64;
#define SGN2 0x8000000080000000ULL
#define ONES2H 0x3C003C00u        // {1.0h, 1.0h}

__device__ __forceinline__ float lg2f_(float x) {
    float r; asm("lg2.approx.ftz.f32 %0, %1;" : "=f"(r) : "f"(x)); return r;
}
// packed f32x2 ops (Blackwell FFMA2 path — PTX-only)
__device__ __forceinline__ u64 fma2_(u64 a, u64 b, u64 c) {
    u64 r; asm("fma.rn.f32x2 %0, %1, %2, %3;" : "=l"(r) : "l"(a), "l"(b), "l"(c)); return r;
}
__device__ __forceinline__ u64 mul2_(u64 a, u64 b) {
    u64 r; asm("mul.rn.f32x2 %0, %1, %2;" : "=l"(r) : "l"(a), "l"(b)); return r;
}
__device__ __forceinline__ u64 add2_(u64 a, u64 b) {
    u64 r; asm("add.rn.f32x2 %0, %1, %2;" : "=l"(r) : "l"(a), "l"(b)); return r;
}
__device__ __forceinline__ void unpack2_(u64 v, float& a, float& b) {
    unsigned lo, hi;
    asm("mov.b64 {%0, %1}, %2;" : "=r"(lo), "=r"(hi) : "l"(v));
    a = __uint_as_float(lo); b = __uint_as_float(hi);
}
__device__ __forceinline__ u64 pack2s_(float x, float y) {
    u64 r; unsigned ux = __float_as_uint(x), uy = __float_as_uint(y);
    asm("mov.b64 %0, {%1, %2};" : "=l"(r) : "r"(ux), "r"(uy));
    return r;
}
__device__ __forceinline__ u64 bcast2_(float v) {
    return pack2s_(v, v);
}
// fp16x2 helpers
__device__ __forceinline__ unsigned f2h2_(float a, float b) {
    unsigned r; asm("cvt.rn.f16x2.f32 %0, %1, %2;" : "=r"(r) : "f"(a), "f"(b)); return r;
}
__device__ __forceinline__ unsigned h2ex2_(unsigned x) {
    unsigned r; asm("ex2.approx.f16x2 %0, %1;" : "=r"(r) : "r"(x)); return r;
}
__device__ __forceinline__ unsigned hadd2_(unsigned a, unsigned b) {
    unsigned r; asm("add.rn.f16x2 %0, %1, %2;" : "=r"(r) : "r"(a), "r"(b)); return r;
}
__device__ __forceinline__ unsigned hmul2_(unsigned a, unsigned b) {
    unsigned r; asm("mul.rn.f16x2 %0, %1, %2;" : "=r"(r) : "r"(a), "r"(b)); return r;
}
__device__ __forceinline__ void h2tof_(unsigned p, float& a, float& b) {
    asm("{\n\t.reg .b16 lo, hi;\n\t"
        "mov.b32 {lo, hi}, %2;\n\t"
        "cvt.f32.f16 %0, lo;\n\t"
        "cvt.f32.f16 %1, hi;\n\t}"
        : "=f"(a), "=f"(b) : "r"(p));
}

#define LOG2E   1.4426950408889634f
#define LN2     0.6931471805599453f
#define LOG10_2 0.3010299956639812f
#define WM  (LN2 / ((float)PIX * (float)N_ * (float)K_))
#define WP  (1.0f / ((float)N_ * K_ * K_))
#define WN  (1.0f / ((float)N_ * 3.0f * K_ * K_))
#define WL  (1.0f / ((float)N_ * K_))

// One pixel, 8 k-values (4 packed k-pairs). Accumulates packed -|z| into accM0/accM1 (fp32 exact),
// returns f16x2 running product of (1+e) factors (4 factors per lane, each in (1,2], <=16).
__device__ __forceinline__ unsigned pixel_prod(
    float f0, float f1, float f2, float f3,
    const u64* C0, const u64* C1, const u64* C2, const u64* C3,
    u64& accM0, u64& accM1)
{
    u64 P0 = bcast2_(f0);
    u64 P1 = bcast2_(f1);
    u64 P2 = bcast2_(f2);
    u64 P3 = bcast2_(f3);
    unsigned P = ONES2H;
#pragma unroll
    for (int kp = 0; kp < 4; ++kp) {
        u64 z = fma2_(C0[kp], P0, fma2_(C1[kp], P1, fma2_(C2[kp], P2, mul2_(C3[kp], P3))));
        u64 m = z | SGN2;               // packed -|z| (fp32, exact path for Sum|z|)
        if (kp & 1) accM1 = add2_(accM1, m);
        else        accM0 = add2_(accM0, m);
        float m0, m1; unpack2_(m, m0, m1);
        unsigned h = f2h2_(m0, m1);     // fp16x2 of -|z|
        unsigned e = h2ex2_(h);         // ONE MUFU for two elements
        unsigned u = hadd2_(e, ONES2H); // 1+e per lane
        P = hmul2_(P, u);
    }
    return P;
}

__global__ __launch_bounds__(T1, 4)
void allloss_kernel(const float* __restrict__ map_class,
                    const float* __restrict__ map_box,
                    const float* __restrict__ map_coef,
                    const float* __restrict__ proto,
                    const float* __restrict__ anchor_center,
                    const float* __restrict__ anchor_hw,
                    const float* __restrict__ gt_boxes,
                    const float* __restrict__ gt_masks,
                    const int*   __restrict__ pos_idx,
                    const int*   __restrict__ neg_idx,
                    const int*   __restrict__ gt_idx,
                    float*       __restrict__ out)
{
    const int bid = blockIdx.x;
    const int tid = threadIdx.x;

    __shared__ float  red[T1];
    __shared__ float  ck[K_][4];      // y blocks
    __shared__ int    bk[K_];
    __shared__ float  Cb[B_][4];
    __shared__ float  Ct[4];

    float partial = 0.0f;

    if (bid < NB_MAIN) {
        // ===== main mask term: sum of lg2(1+2^-|z|) + 0.5*|z|  (0.5*z in y-blocks) =====
        const int n   = bid / (GRP * CH_);
        const int rem = bid % (GRP * CH_);
        const int kg  = rem / CH_;
        const int ch  = rem % CH_;

        // 8 coefficient sets as 4 k-pairs, packed over k
        u64 C0[4], C1[4], C2[4], C3[4];
#pragma unroll
        for (int kp = 0; kp < 4; ++kp) {
            int a0 = pos_idx[n * K_ + kg * G_ + kp * 2 + 0];
            int a1 = pos_idx[n * K_ + kg * G_ + kp * 2 + 1];
            float4 ca = *(const float4*)(map_coef + ((size_t)n * A_ + a0) * 4);
            float4 cb = *(const float4*)(map_coef + ((size_t)n * A_ + a1) * 4);
            C0[kp] = pack2s_(ca.x * LOG2E, cb.x * LOG2E);
            C1[kp] = pack2s_(ca.y * LOG2E, cb.y * LOG2E);
            C2[kp] = pack2s_(ca.z * LOG2E, cb.z * LOG2E);
            C3[kp] = pack2s_(ca.w * LOG2E, cb.w * LOG2E);
        }

        const float* pb = proto + (size_t)n * 4 * PIX;
        const int base = ch * CHPIX + tid * 2;

        u64   accM0 = 0ull, accM1 = 0ull;   // packed sums of -|z| (fp32 exact)
        float acc_lg = 0.0f;

#pragma unroll 1
        for (int it = 0; it < ITERS; ++it) {   // 8 iterations, 2 pixels/thread
            int pix = base + it * (T1 * 2);
            float2 r0 = *(const float2*)(pb + 0 * PIX + pix);
            float2 r1 = *(const float2*)(pb + 1 * PIX + pix);
            float2 r2 = *(const float2*)(pb + 2 * PIX + pix);
            float2 r3 = *(const float2*)(pb + 3 * PIX + pix);

            unsigned PA = pixel_prod(r0.x, r1.x, r2.x, r3.x, C0, C1, C2, C3, accM0, accM1);
            unsigned PB = pixel_prod(r0.y, r1.y, r2.y, r3.y, C0, C1, C2, C3, accM0, accM1);
            unsigned PP = hmul2_(PA, PB);   // 8 factors per lane, <= 256 (fp16-safe)
            float pa, pbf; h2tof_(PP, pa, pbf);
            // one LG2 per 16 elements
            acc_lg += lg2f_(pa * pbf);
        }
        u64 accM = add2_(accM0, accM1);
        float mx, my;
        unpack2_(accM, mx, my);
        // Sum|z| = -(mx+my)
        partial = (acc_lg - 0.5f * (mx + my)) * WM;

    } else if (bid < NB_MAIN + NB_Y) {
        // ===== y-term and 0.5*Sum z term:  sum_pix [ 0.5*(Ctot.p) - sum_b y_b*(C_b.p) ] =====
        const int b2  = bid - NB_MAIN;
        const int n   = b2 >> 3;
        const int ch8 = b2 & 7;

        if (tid < K_) {
            int a = pos_idx[n * K_ + tid];
            const float* cp = map_coef + ((size_t)n * A_ + a) * 4;
            ck[tid][0] = cp[0] * LOG2E; ck[tid][1] = cp[1] * LOG2E;
            ck[tid][2] = cp[2] * LOG2E; ck[tid][3] = cp[3] * LOG2E;
            bk[tid] = gt_idx[n * K_ + tid];
        }
        __syncthreads();
        if (tid < B_ * 4) {
            int b = tid >> 2, j = tid & 3;
            float s = 0.0f;
            for (int k = 0; k < K_; ++k)
                if (bk[k] == b) s += ck[k][j];
            Cb[b][j] = s;
        }
        __syncthreads();
        if (tid < 4) {
            float s = 0.0f;
            for (int b = 0; b < B_; ++b) s += Cb[b][tid];
            Ct[tid] = s;
        }
        __syncthreads();

        const float* pb = proto + (size_t)n * 4 * PIX;
        const float* gm = gt_masks + (size_t)n * B_ * PIX;
        float accD = 0.0f, accE = 0.0f;
#pragma unroll 1
        for (int it = 0; it < 2; ++it) {
            int pix = ch8 * 2048 + (it * T1 + tid) * 4;
            float4 p0 = *(const float4*)(pb + 0 * PIX + pix);
            float4 p1 = *(const float4*)(pb + 1 * PIX + pix);
            float4 p2 = *(const float4*)(pb + 2 * PIX + pix);
            float4 p3 = *(const float4*)(pb + 3 * PIX + pix);
            float t0 = Ct[0], t1 = Ct[1], t2 = Ct[2], t3 = Ct[3];
            accE += fmaf(t0, p0.x, fmaf(t1, p1.x, fmaf(t2, p2.x, t3 * p3.x)));
            accE += fmaf(t0, p0.y, fmaf(t1, p1.y, fmaf(t2, p2.y, t3 * p3.y)));
            accE += fmaf(t0, p0.z, fmaf(t1, p1.z, fmaf(t2, p2.z, t3 * p3.z)));
            accE += fmaf(t0, p0.w, fmaf(t1, p1.w, fmaf(t2, p2.w, t3 * p3.w)));
#pragma unroll
            for (int b = 0; b < B_; ++b) {
                float4 y = *(const float4*)(gm + (size_t)b * PIX + pix);
                float cb0 = Cb[b][0], cb1 = Cb[b][1], cb2 = Cb[b][2], cb3 = Cb[b][3];
                float Zx = fmaf(cb0, p0.x, fmaf(cb1, p1.x, fmaf(cb2, p2.x, cb3 * p3.x)));
                float Zy = fmaf(cb0, p0.y, fmaf(cb1, p1.y, fmaf(cb2, p2.y, cb3 * p3.y)));
                float Zz = fmaf(cb0, p0.z, fmaf(cb1, p1.z, fmaf(cb2, p2.z, cb3 * p3.z)));
                float Zw = fmaf(cb0, p0.w, fmaf(cb1, p1.w, fmaf(cb2, p2.w, cb3 * p3.w)));
                accD = fmaf(y.x, Zx, accD);
                accD = fmaf(y.y, Zy, accD);
                accD = fmaf(y.z, Zz, accD);
                accD = fmaf(y.w, Zw, accD);
            }
        }
        partial = (0.5f * accE - accD) * WM;

    } else {
        // ===== cls (pos+neg) + loc for one image =====
        const int n = bid - NB_MAIN - NB_Y;
        const float EPS = 1e-7f;
        float s = 0.0f;

        if (tid < K_) {
            int a = pos_idx[n * K_ + tid];
            float p = map_class[n * A_ + a];
            p = fminf(fmaxf(p, EPS), 1.0f - EPS);
            s += -lg2f_(p) * (LN2 * WP);

            int gi = gt_idx[n * K_ + tid];
            const float* pr = map_box + ((size_t)n * A_ + a) * 4;
            const float* gt = gt_boxes + ((size_t)n * B_ + gi) * 4;
            float ac0 = anchor_center[a * 2 + 0];
            float ac1 = anchor_center[a * 2 + 1];
            float ah  = anchor_hw[a * 2 + 0];
            float aw  = anchor_hw[a * 2 + 1];
            float t0 = (gt[0] - ac0) / ah;
            float t1 = (gt[1] - ac1) / aw;
            float t2 = lg2f_(gt[2] / ah) * LOG10_2;
            float t3 = lg2f_(gt[3] / aw) * LOG10_2;
            float d, ad, l = 0.0f;
            d = pr[0] - t0; ad = fabsf(d); l += (ad < 1.0f) ? 0.5f * d * d : ad - 0.5f;
            d = pr[1] - t1; ad = fabsf(d); l += (ad < 1.0f) ? 0.5f * d * d : ad - 0.5f;
            d = pr[2] - t2; ad = fabsf(d); l += (ad < 1.0f) ? 0.5f * d * d : ad - 0.5f;
            d = pr[3] - t3; ad = fabsf(d); l += (ad < 1.0f) ? 0.5f * d * d : ad - 0.5f;
            s += l * WL;
        }
        for (int i = tid; i < 3 * K_; i += T1) {
            int a = neg_idx[n * 3 * K_ + i];
            float p = map_class[n * A_ + a];
            p = fminf(fmaxf(p, EPS), 1.0f - EPS);
            s += -lg2f_(1.0f - p) * (LN2 * WN);
        }
        partial = s;
    }

    // ===== block reduction =====
    red[tid] = partial;
    __syncthreads();
#pragma unroll
    for (int st = T1 / 2; st > 0; st >>= 1) {
        if (tid < st) red[tid] += red[tid + st];
        __syncthreads();
    }
    if (tid == 0) g_partials[bid] = red[0];

    // ===== last-block final reduction =====
    __shared__ bool isLast;
    if (tid == 0) {
        __threadfence();
        unsigned int old = atomicAdd(&g_count, 1u);
        isLast = (old == NPART - 1);
    }
    __syncthreads();
    if (isLast) {
        float s = 0.0f;
        for (int i = tid; i < NPART; i += T1) s += g_partials[i];
        red[tid] = s;
        __syncthreads();
#pragma unroll
        for (int st = T1 / 2; st > 0; st >>= 1) {
            if (tid < st) red[tid] += red[tid + st];
            __syncthreads();
        }
        if (tid == 0) {
            out[0] = red[0];
            g_count = 0;
        }
    }
}

extern "C" void kernel_launch(void* const* d_in, const int* in_sizes, int n_in,
                              void* d_out, int out_size)
{
    const float* map_class     = (const float*)d_in[0];
    const float* map_box       = (const float*)d_in[1];
    const float* map_coef      = (const float*)d_in[2];
    const float* proto         = (const float*)d_in[3];
    const float* anchor_center = (const float*)d_in[4];
    const float* anchor_hw     = (const float*)d_in[5];
    const float* gt_boxes      = (const float*)d_in[6];
    const float* gt_masks      = (const float*)d_in[7];
    const int*   pos_idx       = (const int*)d_in[8];
    const int*   neg_idx       = (const int*)d_in[9];
    const int*   gt_idx        = (const int*)d_in[10];
    float* out = (float*)d_out;

    allloss_kernel<<<NPART, T1>>>(map_class, map_box, map_coef, proto,
                                  anchor_center, anchor_hw, gt_boxes, gt_masks,
                                  pos_idx, neg_idx, gt_idx, out);
}

// round 15
// speedup vs baseline: 1.3176x; 1.1115x over previous
#include <cuda_runtime.h>
#include <math.h>

// Problem constants
#define N_    8
#define A_    16368
#define K_    200
#define B_    20
#define PIX   16384           // 128*128
#define G_    8               // k-values per main block (4 packed k-pairs in regs)
#define GRP   (K_ / G_)       // 25
#define CH_   4               // pixel chunks per (n, k-group)
#define CHPIX (PIX / CH_)     // 4096
#define NB_MAIN (N_ * GRP * CH_)   // 800
#define NB_Y    (N_ * 8)           // 64
#define NB_MISC (N_)               // 8
#define NPART   (NB_MAIN + NB_Y + NB_MISC)  // 872
#define T1    256
#define ITERS (CHPIX / (T1 * 2))   // 8 iterations, 2 pixels/thread

__device__ float g_partials[NPART];
__device__ unsigned int g_count;   // zero-init; reset by final block each call

typedef unsigned long long u64;

__device__ __forceinline__ float ex2f_(float x) {
    float r; asm("ex2.approx.ftz.f32 %0, %1;" : "=f"(r) : "f"(x)); return r;
}
__device__ __forceinline__ float lg2f_(float x) {
    float r; asm("lg2.approx.ftz.f32 %0, %1;" : "=f"(r) : "f"(x)); return r;
}
// packed f32x2 ops (Blackwell FFMA2 path — PTX-only)
__device__ __forceinline__ u64 fma2_(u64 a, u64 b, u64 c) {
    u64 r; asm("fma.rn.f32x2 %0, %1, %2, %3;" : "=l"(r) : "l"(a), "l"(b), "l"(c)); return r;
}
__device__ __forceinline__ u64 mul2_(u64 a, u64 b) {
    u64 r; asm("mul.rn.f32x2 %0, %1, %2;" : "=l"(r) : "l"(a), "l"(b)); return r;
}
__device__ __forceinline__ void unpack2_(u64 v, float& a, float& b) {
    unsigned lo, hi;
    asm("mov.b64 {%0, %1}, %2;" : "=r"(lo), "=r"(hi) : "l"(v));
    a = __uint_as_float(lo); b = __uint_as_float(hi);
}
__device__ __forceinline__ u64 pack2s_(float x, float y) {
    u64 r; unsigned ux = __float_as_uint(x), uy = __float_as_uint(y);
    asm("mov.b64 %0, {%1, %2};" : "=l"(r) : "r"(ux), "r"(uy));
    return r;
}
__device__ __forceinline__ u64 bcast2_(float v) {
    return pack2s_(v, v);
}

#define LOG2E   1.4426950408889634f
#define HLOG2E  0.7213475204444817f   // log2(e)/2
#define LN2     0.6931471805599453f
#define LOG10_2 0.3010299956639812f
#define WM  (LN2 / ((float)PIX * (float)N_ * (float)K_))
#define WP  (1.0f / ((float)N_ * K_ * K_))
#define WN  (1.0f / ((float)N_ * 3.0f * K_ * K_))
#define WL  (1.0f / ((float)N_ * K_))

// One pixel, 8 k-values (4 packed k-pairs with BROADCAST pixel operands).
// softplus2(z) = lg2(2^z + 1) = lg2(e*e + 1), e = 2^(z/2); coefficients pre-scaled by log2e/2.
// Adds lg2 of the 8-factor product to acc_lg (factors >= 1, exponent sum <= ~60 bits).
__device__ __forceinline__ void pixel_sp(
    float f0, float f1, float f2, float f3,
    const u64* C0, const u64* C1, const u64* C2, const u64* C3,
    float& acc_lg)
{
    u64 P0 = bcast2_(f0);
    u64 P1 = bcast2_(f1);
    u64 P2 = bcast2_(f2);
    u64 P3 = bcast2_(f3);
    float t0, t1, t2, t3;
    {
        u64 z = fma2_(C0[0], P0, fma2_(C1[0], P1, fma2_(C2[0], P2, mul2_(C3[0], P3))));
        float z0, z1; unpack2_(z, z0, z1);
        float e0 = ex2f_(z0), e1 = ex2f_(z1);
        t0 = fmaf(e0, e0, 1.0f) * fmaf(e1, e1, 1.0f);
    }
    {
        u64 z = fma2_(C0[1], P0, fma2_(C1[1], P1, fma2_(C2[1], P2, mul2_(C3[1], P3))));
        float z0, z1; unpack2_(z, z0, z1);
        float e0 = ex2f_(z0), e1 = ex2f_(z1);
        t1 = fmaf(e0, e0, 1.0f) * fmaf(e1, e1, 1.0f);
    }
    {
        u64 z = fma2_(C0[2], P0, fma2_(C1[2], P1, fma2_(C2[2], P2, mul2_(C3[2], P3))));
        float z0, z1; unpack2_(z, z0, z1);
        float e0 = ex2f_(z0), e1 = ex2f_(z1);
        t2 = fmaf(e0, e0, 1.0f) * fmaf(e1, e1, 1.0f);
    }
    {
        u64 z = fma2_(C0[3], P0, fma2_(C1[3], P1, fma2_(C2[3], P2, mul2_(C3[3], P3))));
        float z0, z1; unpack2_(z, z0, z1);
        float e0 = ex2f_(z0), e1 = ex2f_(z1);
        t3 = fmaf(e0, e0, 1.0f) * fmaf(e1, e1, 1.0f);
    }
    acc_lg += lg2f_((t0 * t1) * (t2 * t3));   // one LG2 per 8 elements
}

__global__ __launch_bounds__(T1, 4)
void allloss_kernel(const float* __restrict__ map_class,
                    const float* __restrict__ map_box,
                    const float* __restrict__ map_coef,
                    const float* __restrict__ proto,
                    const float* __restrict__ anchor_center,
                    const float* __restrict__ anchor_hw,
                    const float* __restrict__ gt_boxes,
                    const float* __restrict__ gt_masks,
                    const int*   __restrict__ pos_idx,
                    const int*   __restrict__ neg_idx,
                    const int*   __restrict__ gt_idx,
                    float*       __restrict__ out)
{
    const int bid = blockIdx.x;
    const int tid = threadIdx.x;

    __shared__ float  red[T1];
    __shared__ float  ck[K_][4];      // y blocks
    __shared__ int    bk[K_];
    __shared__ float  Cb[B_][4];

    float partial = 0.0f;

    if (bid < NB_MAIN) {
        // ===== main mask term: sum of lg2(1 + 2^z)  (y-term handled in y-blocks) =====
        const int n   = bid / (GRP * CH_);
        const int rem = bid % (GRP * CH_);
        const int kg  = rem / CH_;
        const int ch  = rem % CH_;

        // 8 coefficient sets as 4 k-pairs, packed over k, scaled by log2(e)/2
        u64 C0[4], C1[4], C2[4], C3[4];
#pragma unroll
        for (int kp = 0; kp < 4; ++kp) {
            int a0 = pos_idx[n * K_ + kg * G_ + kp * 2 + 0];
            int a1 = pos_idx[n * K_ + kg * G_ + kp * 2 + 1];
            float4 ca = *(const float4*)(map_coef + ((size_t)n * A_ + a0) * 4);
            float4 cb = *(const float4*)(map_coef + ((size_t)n * A_ + a1) * 4);
            C0[kp] = pack2s_(ca.x * HLOG2E, cb.x * HLOG2E);
            C1[kp] = pack2s_(ca.y * HLOG2E, cb.y * HLOG2E);
            C2[kp] = pack2s_(ca.z * HLOG2E, cb.z * HLOG2E);
            C3[kp] = pack2s_(ca.w * HLOG2E, cb.w * HLOG2E);
        }

        const float* pb = proto + (size_t)n * 4 * PIX;
        const int base = ch * CHPIX + tid * 2;

        float acc_lg = 0.0f;

#pragma unroll 1
        for (int it = 0; it < ITERS; ++it) {   // 8 iterations, 2 pixels/thread
            int pix = base + it * (T1 * 2);
            float2 r0 = *(const float2*)(pb + 0 * PIX + pix);
            float2 r1 = *(const float2*)(pb + 1 * PIX + pix);
            float2 r2 = *(const float2*)(pb + 2 * PIX + pix);
            float2 r3 = *(const float2*)(pb + 3 * PIX + pix);

            pixel_sp(r0.x, r1.x, r2.x, r3.x, C0, C1, C2, C3, acc_lg);
            pixel_sp(r0.y, r1.y, r2.y, r3.y, C0, C1, C2, C3, acc_lg);
        }
        partial = acc_lg * WM;

    } else if (bid < NB_MAIN + NB_Y) {
        // ===== y-term only:  -sum_pix sum_b y_b(pix) * (C_b . p(pix))   (z in log2 units)
        const int b2  = bid - NB_MAIN;
        const int n   = b2 >> 3;
        const int ch8 = b2 & 7;

        if (tid < K_) {
            int a = pos_idx[n * K_ + tid];
            const float* cp = map_coef + ((size_t)n * A_ + a) * 4;
            ck[tid][0] = cp[0] * LOG2E; ck[tid][1] = cp[1] * LOG2E;
            ck[tid][2] = cp[2] * LOG2E; ck[tid][3] = cp[3] * LOG2E;
            bk[tid] = gt_idx[n * K_ + tid];
        }
        __syncthreads();
        if (tid < B_ * 4) {
            int b = tid >> 2, j = tid & 3;
            float s = 0.0f;
            for (int k = 0; k < K_; ++k)
                if (bk[k] == b) s += ck[k][j];
            Cb[b][j] = s;
        }
        __syncthreads();

        const float* pb = proto + (size_t)n * 4 * PIX;
        const float* gm = gt_masks + (size_t)n * B_ * PIX;
        float accD = 0.0f;
#pragma unroll 1
        for (int it = 0; it < 2; ++it) {
            int pix = ch8 * 2048 + (it * T1 + tid) * 4;
            float4 p0 = *(const float4*)(pb + 0 * PIX + pix);
            float4 p1 = *(const float4*)(pb + 1 * PIX + pix);
            float4 p2 = *(const float4*)(pb + 2 * PIX + pix);
            float4 p3 = *(const float4*)(pb + 3 * PIX + pix);
#pragma unroll
            for (int b = 0; b < B_; ++b) {
                float4 y = *(const float4*)(gm + (size_t)b * PIX + pix);
                float cb0 = Cb[b][0], cb1 = Cb[b][1], cb2 = Cb[b][2], cb3 = Cb[b][3];
                float Zx = fmaf(cb0, p0.x, fmaf(cb1, p1.x, fmaf(cb2, p2.x, cb3 * p3.x)));
                float Zy = fmaf(cb0, p0.y, fmaf(cb1, p1.y, fmaf(cb2, p2.y, cb3 * p3.y)));
                float Zz = fmaf(cb0, p0.z, fmaf(cb1, p1.z, fmaf(cb2, p2.z, cb3 * p3.z)));
                float Zw = fmaf(cb0, p0.w, fmaf(cb1, p1.w, fmaf(cb2, p2.w, cb3 * p3.w)));
                accD = fmaf(y.x, Zx, accD);
                accD = fmaf(y.y, Zy, accD);
                accD = fmaf(y.z, Zz, accD);
                accD = fmaf(y.w, Zw, accD);
            }
        }
        partial = -accD * WM;

    } else {
        // ===== cls (pos+neg) + loc for one image =====
        const int n = bid - NB_MAIN - NB_Y;
        const float EPS = 1e-7f;
        float s = 0.0f;

        if (tid < K_) {
            int a = pos_idx[n * K_ + tid];
            float p = map_class[n * A_ + a];
            p = fminf(fmaxf(p, EPS), 1.0f - EPS);
            s += -lg2f_(p) * (LN2 * WP);

            int gi = gt_idx[n * K_ + tid];
            const float* pr = map_box + ((size_t)n * A_ + a) * 4;
            const float* gt = gt_boxes + ((size_t)n * B_ + gi) * 4;
            float ac0 = anchor_center[a * 2 + 0];
            float ac1 = anchor_center[a * 2 + 1];
            float ah  = anchor_hw[a * 2 + 0];
            float aw  = anchor_hw[a * 2 + 1];
            float t0 = (gt[0] - ac0) / ah;
            float t1 = (gt[1] - ac1) / aw;
            float t2 = lg2f_(gt[2] / ah) * LOG10_2;
            float t3 = lg2f_(gt[3] / aw) * LOG10_2;
            float d, ad, l = 0.0f;
            d = pr[0] - t0; ad = fabsf(d); l += (ad < 1.0f) ? 0.5f * d * d : ad - 0.5f;
            d = pr[1] - t1; ad = fabsf(d); l += (ad < 1.0f) ? 0.5f * d * d : ad - 0.5f;
            d = pr[2] - t2; ad = fabsf(d); l += (ad < 1.0f) ? 0.5f * d * d : ad - 0.5f;
            d = pr[3] - t3; ad = fabsf(d); l += (ad < 1.0f) ? 0.5f * d * d : ad - 0.5f;
            s += l * WL;
        }
        for (int i = tid; i < 3 * K_; i += T1) {
            int a = neg_idx[n * 3 * K_ + i];
            float p = map_class[n * A_ + a];
            p = fminf(fmaxf(p, EPS), 1.0f - EPS);
            s += -lg2f_(1.0f - p) * (LN2 * WN);
        }
        partial = s;
    }

    // ===== block reduction =====
    red[tid] = partial;
    __syncthreads();
#pragma unroll
    for (int st = T1 / 2; st > 0; st >>= 1) {
        if (tid < st) red[tid] += red[tid + st];
        __syncthreads();
    }
    if (tid == 0) g_partials[bid] = red[0];

    // ===== last-block final reduction =====
    __shared__ bool isLast;
    if (tid == 0) {
        __threadfence();
        unsigned int old = atomicAdd(&g_count, 1u);
        isLast = (old == NPART - 1);
    }
    __syncthreads();
    if (isLast) {
        float s = 0.0f;
        for (int i = tid; i < NPART; i += T1) s += g_partials[i];
        red[tid] = s;
        __syncthreads();
#pragma unroll
        for (int st = T1 / 2; st > 0; st >>= 1) {
            if (tid < st) red[tid] += red[tid + st];
            __syncthreads();
        }
        if (tid == 0) {
            out[0] = red[0];
            g_count = 0;
        }
    }
}

extern "C" void kernel_launch(void* const* d_in, const int* in_sizes, int n_in,
                              void* d_out, int out_size)
{
    const float* map_class     = (const float*)d_in[0];
    const float* map_box       = (const float*)d_in[1];
    const float* map_coef      = (const float*)d_in[2];
    const float* proto         = (const float*)d_in[3];
    const float* anchor_center = (const float*)d_in[4];
    const float* anchor_hw     = (const float*)d_in[5];
    const float* gt_boxes      = (const float*)d_in[6];
    const float* gt_masks      = (const float*)d_in[7];
    const int*   pos_idx       = (const int*)d_in[8];
    const int*   neg_idx       = (const int*)d_in[9];
    const int*   gt_idx        = (const int*)d_in[10];
    float* out = (float*)d_out;

    allloss_kernel<<<NPART, T1>>>(map_class, map_box, map_coef, proto,
                                  anchor_center, anchor_hw, gt_boxes, gt_masks,
                                  pos_idx, neg_idx, gt_idx, out);
}